// round 1
// baseline (speedup 1.0000x reference)
#include <cuda_runtime.h>
#include <math.h>

#define BB 2
#define CC 128
#define NN 4096
#define NG 32
#define CPG 4
#define KSLICES 4

// scratch (static device globals; no allocation allowed)
__device__ float g_h[BB*CC*NN];
__device__ float g_q[BB*CC*NN];
__device__ float g_k[BB*CC*NN];
__device__ float g_v[BB*CC*NN];
__device__ float g_o[BB*CC*NN];
__device__ float g_opart[KSLICES*BB*CC*NN];
__device__ float g_S[(size_t)BB*NN*NN];   // 128 MiB scores / probs (in-place)

// ---------------------------------------------------------------------------
// GroupNorm: one block per (batch, group). Group = 4 channels * 4096 = 16384
// contiguous floats.
// ---------------------------------------------------------------------------
__global__ void gn_kernel(const float* __restrict__ x,
                          const float* __restrict__ gamma,
                          const float* __restrict__ beta) {
    const int bg = blockIdx.x;
    const int b = bg / NG, g = bg % NG;
    const size_t base = ((size_t)b*CC + g*CPG) * NN;
    const float* xp = x + base;
    const int M = CPG*NN;  // 16384

    float s = 0.f, s2 = 0.f;
    for (int i = threadIdx.x; i < M; i += 256) {
        float v = xp[i]; s += v; s2 += v*v;
    }
    __shared__ float sh0[8], sh1[8];
    #pragma unroll
    for (int o = 16; o; o >>= 1) {
        s  += __shfl_xor_sync(0xffffffffu, s,  o);
        s2 += __shfl_xor_sync(0xffffffffu, s2, o);
    }
    if ((threadIdx.x & 31) == 0) { sh0[threadIdx.x>>5] = s; sh1[threadIdx.x>>5] = s2; }
    __syncthreads();
    float ts = 0.f, ts2 = 0.f;
    #pragma unroll
    for (int i = 0; i < 8; i++) { ts += sh0[i]; ts2 += sh1[i]; }
    const float mean = ts / (float)M;
    const float var  = ts2 / (float)M - mean*mean;
    const float inv  = rsqrtf(var + 1e-5f);

    float* hp = g_h + base;
    for (int i = threadIdx.x; i < M; i += 256) {
        int c = g*CPG + (i >> 12);
        hp[i] = (xp[i] - mean) * inv * gamma[c] + beta[c];
    }
}

// ---------------------------------------------------------------------------
// 1x1 conv as GEMM: out[o][n] = sum_c W[o][c]*H[c][n] + bias[o] (+resid)
// 64x64 tile, 256 threads, 4x4 microtile, BK=16.
// ---------------------------------------------------------------------------
__global__ __launch_bounds__(256) void conv_kernel(
    const float* __restrict__ W, const float* __restrict__ bias,
    const float* __restrict__ H, const float* __restrict__ resid,
    float* __restrict__ out)
{
    const int b  = blockIdx.z;
    const int n0 = blockIdx.x * 64;
    const int o0 = blockIdx.y * 64;
    const float* Hb = H + (size_t)b*CC*NN;

    __shared__ __align__(16) float As[16][68];   // [c'][o]  (transposed W tile)
    __shared__ __align__(16) float Bs[16][64];   // [c'][n]
    const int tid = threadIdx.x;
    const int tx = tid & 15, ty = tid >> 4;
    float acc[4][4] = {};

    for (int kc = 0; kc < CC; kc += 16) {
        {
            int o = tid >> 2, f4 = tid & 3;
            float4 w4 = *(const float4*)&W[(size_t)(o0+o)*CC + kc + f4*4];
            As[f4*4+0][o] = w4.x; As[f4*4+1][o] = w4.y;
            As[f4*4+2][o] = w4.z; As[f4*4+3][o] = w4.w;
        }
        {
            int r = tid >> 4, c4 = tid & 15;
            *(float4*)&Bs[r][c4*4] =
                *(const float4*)&Hb[(size_t)(kc+r)*NN + n0 + c4*4];
        }
        __syncthreads();
        #pragma unroll
        for (int kk = 0; kk < 16; kk++) {
            float a[4], bb[4];
            *(float4*)a  = *(const float4*)&As[kk][ty*4];
            *(float4*)bb = *(const float4*)&Bs[kk][tx*4];
            #pragma unroll
            for (int i = 0; i < 4; i++)
                #pragma unroll
                for (int j = 0; j < 4; j++)
                    acc[i][j] = fmaf(a[i], bb[j], acc[i][j]);
        }
        __syncthreads();
    }

    const size_t ob = (size_t)b*CC*NN;
    #pragma unroll
    for (int i = 0; i < 4; i++) {
        const int o = o0 + ty*4 + i;
        const float bi = bias[o];
        const size_t rowoff = ob + (size_t)o*NN + n0 + tx*4;
        float4 v;
        v.x = acc[i][0] + bi; v.y = acc[i][1] + bi;
        v.z = acc[i][2] + bi; v.w = acc[i][3] + bi;
        if (resid) {
            float4 r4 = *(const float4*)&resid[rowoff];
            v.x += r4.x; v.y += r4.y; v.z += r4.z; v.w += r4.w;
        }
        *(float4*)&out[rowoff] = v;
    }
}

// ---------------------------------------------------------------------------
// S[n][m] = scale * sum_c q[c][n]*k[c][m].  128x128 tile, 8x8 microtile.
// ---------------------------------------------------------------------------
__global__ __launch_bounds__(256) void qk_kernel() {
    const int b  = blockIdx.z;
    const int n0 = blockIdx.x * 128;
    const int m0 = blockIdx.y * 128;
    const float* q = g_q + (size_t)b*CC*NN;
    const float* k = g_k + (size_t)b*CC*NN;
    float* S = g_S + (size_t)b*NN*NN;

    __shared__ __align__(16) float As[16][128];  // [c'][n]
    __shared__ __align__(16) float Bs[16][128];  // [c'][m]
    const int tid = threadIdx.x;
    const int tx = tid & 15, ty = tid >> 4;
    float acc[8][8] = {};

    for (int kc = 0; kc < CC; kc += 16) {
        #pragma unroll
        for (int i = 0; i < 2; i++) {
            int idx = tid + i*256;
            int r = idx >> 5, c4 = idx & 31;
            *(float4*)&As[r][c4*4] = *(const float4*)&q[(size_t)(kc+r)*NN + n0 + c4*4];
            *(float4*)&Bs[r][c4*4] = *(const float4*)&k[(size_t)(kc+r)*NN + m0 + c4*4];
        }
        __syncthreads();
        #pragma unroll
        for (int kk = 0; kk < 16; kk++) {
            float a[8], bb[8];
            *(float4*)&a[0]  = *(const float4*)&As[kk][ty*8];
            *(float4*)&a[4]  = *(const float4*)&As[kk][ty*8+4];
            *(float4*)&bb[0] = *(const float4*)&Bs[kk][tx*8];
            *(float4*)&bb[4] = *(const float4*)&Bs[kk][tx*8+4];
            #pragma unroll
            for (int i = 0; i < 8; i++)
                #pragma unroll
                for (int j = 0; j < 8; j++)
                    acc[i][j] = fmaf(a[i], bb[j], acc[i][j]);
        }
        __syncthreads();
    }

    const float scale = 0.0883883476483184f;  // 128^-0.5
    #pragma unroll
    for (int i = 0; i < 8; i++) {
        const int n = n0 + ty*8 + i;
        #pragma unroll
        for (int j = 0; j < 8; j += 4) {
            float4 v;
            v.x = acc[i][j+0]*scale; v.y = acc[i][j+1]*scale;
            v.z = acc[i][j+2]*scale; v.w = acc[i][j+3]*scale;
            *(float4*)&S[(size_t)n*NN + m0 + tx*8 + j] = v;
        }
    }
}

// ---------------------------------------------------------------------------
// Fast exp via FMA pipe (avoid MUFU bottleneck: 33.5M exps).
// Valid for x <= 0 (post max-subtraction). rel err ~3e-5.
// ---------------------------------------------------------------------------
__device__ __forceinline__ float fast_exp(float x) {
    float t = fmaxf(x * 1.44269504088896341f, -126.0f);
    float fi = floorf(t);
    float p = (t - fi) * 0.69314718055994531f;     // in [0, ln2)
    float r = 1.3888888888888889e-3f;              // 1/720
    r = fmaf(r, p, 8.3333333333333333e-3f);        // 1/120
    r = fmaf(r, p, 4.1666666666666664e-2f);        // 1/24
    r = fmaf(r, p, 1.6666666666666666e-1f);        // 1/6
    r = fmaf(r, p, 0.5f);
    r = fmaf(r, p, 1.0f);
    r = fmaf(r, p, 1.0f);
    float sc = __int_as_float(((int)fi + 127) << 23);
    return r * sc;
}

// ---------------------------------------------------------------------------
// Row softmax over 4096 entries. Row resident in registers (16 floats/thread).
// ---------------------------------------------------------------------------
__global__ void softmax_kernel() {
    float4* S = ((float4*)g_S) + (size_t)blockIdx.x * (NN/4);
    const int tid = threadIdx.x;
    __shared__ float sh[8];

    float4 v[4];
    float mx = -3.0e38f;
    #pragma unroll
    for (int i = 0; i < 4; i++) {
        v[i] = S[tid + i*256];
        mx = fmaxf(mx, fmaxf(fmaxf(v[i].x, v[i].y), fmaxf(v[i].z, v[i].w)));
    }
    #pragma unroll
    for (int o = 16; o; o >>= 1) mx = fmaxf(mx, __shfl_xor_sync(0xffffffffu, mx, o));
    if ((tid & 31) == 0) sh[tid >> 5] = mx;
    __syncthreads();
    mx = sh[0];
    #pragma unroll
    for (int i = 1; i < 8; i++) mx = fmaxf(mx, sh[i]);
    __syncthreads();

    float sum = 0.f;
    #pragma unroll
    for (int i = 0; i < 4; i++) {
        v[i].x = fast_exp(v[i].x - mx); v[i].y = fast_exp(v[i].y - mx);
        v[i].z = fast_exp(v[i].z - mx); v[i].w = fast_exp(v[i].w - mx);
        sum += (v[i].x + v[i].y) + (v[i].z + v[i].w);
    }
    #pragma unroll
    for (int o = 16; o; o >>= 1) sum += __shfl_xor_sync(0xffffffffu, sum, o);
    if ((tid & 31) == 0) sh[tid >> 5] = sum;
    __syncthreads();
    float tot = 0.f;
    #pragma unroll
    for (int i = 0; i < 8; i++) tot += sh[i];
    const float inv = 1.0f / tot;

    #pragma unroll
    for (int i = 0; i < 4; i++) {
        v[i].x *= inv; v[i].y *= inv; v[i].z *= inv; v[i].w *= inv;
        S[tid + i*256] = v[i];
    }
}

// ---------------------------------------------------------------------------
// O[c][n] = sum_m P[n][m]*v[c][m].  128(c) x 128(n) tile, split-K x4.
// ---------------------------------------------------------------------------
__global__ __launch_bounds__(256) void pv_kernel() {
    const int b  = blockIdx.z;
    const int n0 = blockIdx.x * 128;
    const int ks = blockIdx.y;
    const int mbase = ks * (NN / KSLICES);
    const float* vv = g_v + (size_t)b*CC*NN;
    const float* P  = g_S + (size_t)b*NN*NN;
    float* O = g_opart + ((size_t)(ks*BB + b))*CC*NN;

    __shared__ __align__(16) float As[16][132];  // [m'][c]
    __shared__ __align__(16) float Bs[16][132];  // [m'][n]
    const int tid = threadIdx.x;
    const int tx = tid & 15, ty = tid >> 4;
    float acc[8][8] = {};

    for (int mc = 0; mc < NN/KSLICES; mc += 16) {
        const int m0 = mbase + mc;
        #pragma unroll
        for (int i = 0; i < 2; i++) {
            int idx = tid + i*256;
            int r = idx >> 2, f4 = idx & 3;   // r: c for A, n' for B
            float4 a4 = *(const float4*)&vv[(size_t)r*NN + m0 + f4*4];
            As[f4*4+0][r] = a4.x; As[f4*4+1][r] = a4.y;
            As[f4*4+2][r] = a4.z; As[f4*4+3][r] = a4.w;
            float4 p4 = *(const float4*)&P[(size_t)(n0+r)*NN + m0 + f4*4];
            Bs[f4*4+0][r] = p4.x; Bs[f4*4+1][r] = p4.y;
            Bs[f4*4+2][r] = p4.z; Bs[f4*4+3][r] = p4.w;
        }
        __syncthreads();
        #pragma unroll
        for (int kk = 0; kk < 16; kk++) {
            float a[8], bb[8];
            *(float4*)&a[0]  = *(const float4*)&As[kk][ty*8];
            *(float4*)&a[4]  = *(const float4*)&As[kk][ty*8+4];
            *(float4*)&bb[0] = *(const float4*)&Bs[kk][tx*8];
            *(float4*)&bb[4] = *(const float4*)&Bs[kk][tx*8+4];
            #pragma unroll
            for (int i = 0; i < 8; i++)
                #pragma unroll
                for (int j = 0; j < 8; j++)
                    acc[i][j] = fmaf(a[i], bb[j], acc[i][j]);
        }
        __syncthreads();
    }

    #pragma unroll
    for (int i = 0; i < 8; i++) {
        const int c = ty*8 + i;
        #pragma unroll
        for (int j = 0; j < 8; j += 4) {
            float4 v4;
            v4.x = acc[i][j+0]; v4.y = acc[i][j+1];
            v4.z = acc[i][j+2]; v4.w = acc[i][j+3];
            *(float4*)&O[(size_t)c*NN + n0 + tx*8 + j] = v4;
        }
    }
}

// Sum the KSLICES partial O buffers.
__global__ void reduce_o_kernel() {
    const size_t i = ((size_t)blockIdx.x*256 + threadIdx.x) * 4;
    const size_t stride = (size_t)BB*CC*NN;
    float4 a = *(const float4*)&g_opart[i];
    #pragma unroll
    for (int s = 1; s < KSLICES; s++) {
        float4 p = *(const float4*)&g_opart[s*stride + i];
        a.x += p.x; a.y += p.y; a.z += p.z; a.w += p.w;
    }
    *(float4*)&g_o[i] = a;
}

// ---------------------------------------------------------------------------
extern "C" void kernel_launch(void* const* d_in, const int* in_sizes, int n_in,
                              void* d_out, int out_size) {
    const float* x   = (const float*)d_in[0];
    const float* gnw = (const float*)d_in[1];
    const float* gnb = (const float*)d_in[2];
    const float* wq  = (const float*)d_in[3];
    const float* bq  = (const float*)d_in[4];
    const float* wk  = (const float*)d_in[5];
    const float* bk  = (const float*)d_in[6];
    const float* wv  = (const float*)d_in[7];
    const float* bv  = (const float*)d_in[8];
    const float* wp  = (const float*)d_in[9];
    const float* bp  = (const float*)d_in[10];
    float* out = (float*)d_out;

    float *ph, *pq, *pk, *pv_, *po;
    cudaGetSymbolAddress((void**)&ph,  g_h);
    cudaGetSymbolAddress((void**)&pq,  g_q);
    cudaGetSymbolAddress((void**)&pk,  g_k);
    cudaGetSymbolAddress((void**)&pv_, g_v);
    cudaGetSymbolAddress((void**)&po,  g_o);

    gn_kernel<<<BB*NG, 256>>>(x, gnw, gnb);

    dim3 cg(NN/64, CC/64, BB);
    conv_kernel<<<cg, 256>>>(wq, bq, ph, nullptr, pq);
    conv_kernel<<<cg, 256>>>(wk, bk, ph, nullptr, pk);
    conv_kernel<<<cg, 256>>>(wv, bv, ph, nullptr, pv_);

    dim3 sg(NN/128, NN/128, BB);
    qk_kernel<<<sg, 256>>>();

    softmax_kernel<<<BB*NN, 256>>>();

    dim3 pg(NN/128, KSLICES, BB);
    pv_kernel<<<pg, 256>>>();
    reduce_o_kernel<<<(BB*CC*NN)/1024, 256>>>();

    conv_kernel<<<cg, 256>>>(wp, bp, po, x, out);
}

// round 2
// speedup vs baseline: 3.2734x; 3.2734x over previous
#include <cuda_runtime.h>
#include <cuda_bf16.h>
#include <math.h>
#include <stdint.h>

#define BB 2
#define CC 128
#define NN 4096
#define NG 32
#define CPG 4
#define KSLICES 4

// ---------------- scratch (static device globals) ----------------
__device__ float          g_h[BB*CC*NN];                 // GN output [b][c][n] fp32
__device__ __nv_bfloat16  g_qt[BB*NN*CC];                // Q^T [b][n][c] bf16 (scale folded)
__device__ __nv_bfloat16  g_kb[BB*CC*NN];                // K   [b][c][n] bf16
__device__ __nv_bfloat16  g_vt[BB*NN*CC];                // V^T [b][n][c] bf16
__device__ __nv_bfloat16  g_S[(size_t)BB*NN*NN];         // scores / probs bf16 (64 MiB)
__device__ float          g_opart[KSLICES*BB*NN*CC];     // split-K partials [s][b][n][c]
__device__ float          g_ot[BB*NN*CC];                // attention out [b][n][c] fp32

// ---------------------------------------------------------------------------
// GroupNorm: one block per (batch, group). fp32 output.
// ---------------------------------------------------------------------------
__global__ void gn_kernel(const float* __restrict__ x,
                          const float* __restrict__ gamma,
                          const float* __restrict__ beta) {
    const int bg = blockIdx.x;
    const int b = bg / NG, g = bg % NG;
    const size_t base = ((size_t)b*CC + g*CPG) * NN;
    const float* xp = x + base;
    const int M = CPG*NN;

    float s = 0.f, s2 = 0.f;
    for (int i = threadIdx.x; i < M; i += 256) {
        float v = xp[i]; s += v; s2 += v*v;
    }
    __shared__ float sh0[8], sh1[8];
    #pragma unroll
    for (int o = 16; o; o >>= 1) {
        s  += __shfl_xor_sync(0xffffffffu, s,  o);
        s2 += __shfl_xor_sync(0xffffffffu, s2, o);
    }
    if ((threadIdx.x & 31) == 0) { sh0[threadIdx.x>>5] = s; sh1[threadIdx.x>>5] = s2; }
    __syncthreads();
    float ts = 0.f, ts2 = 0.f;
    #pragma unroll
    for (int i = 0; i < 8; i++) { ts += sh0[i]; ts2 += sh1[i]; }
    const float mean = ts / (float)M;
    const float var  = ts2 / (float)M - mean*mean;
    const float inv  = rsqrtf(var + 1e-5f);

    float* hp = g_h + base;
    for (int i = threadIdx.x; i < M; i += 256) {
        int c = g*CPG + (i >> 12);
        hp[i] = (xp[i] - mean) * inv * gamma[c] + beta[c];
    }
}

// ---------------------------------------------------------------------------
// Fused QKV 1x1 convs. 64x64 tile, 4x4 microtile, BK=16, 3 accumulators.
// q -> g_qt [n][c] bf16 (scaled by C^-0.5), k -> g_kb [c][n] bf16,
// v -> g_vt [n][c] bf16.
// ---------------------------------------------------------------------------
__global__ __launch_bounds__(256) void conv_qkv_kernel(
    const float* __restrict__ Wq, const float* __restrict__ bq,
    const float* __restrict__ Wk, const float* __restrict__ bk,
    const float* __restrict__ Wv, const float* __restrict__ bv)
{
    const int b  = blockIdx.z;
    const int n0 = blockIdx.x * 64;
    const int o0 = blockIdx.y * 64;
    const float* Hb = g_h + (size_t)b*CC*NN;

    __shared__ __align__(16) float Aq[16][68], Ak[16][68], Av[16][68];
    __shared__ __align__(16) float Bs[16][64];
    const int tid = threadIdx.x;
    const int tx = tid & 15, ty = tid >> 4;
    float aq[4][4] = {}, ak[4][4] = {}, av[4][4] = {};

    for (int kc = 0; kc < CC; kc += 16) {
        {
            int o = tid >> 2, f4 = tid & 3;
            float4 w;
            w = *(const float4*)&Wq[(size_t)(o0+o)*CC + kc + f4*4];
            Aq[f4*4+0][o] = w.x; Aq[f4*4+1][o] = w.y; Aq[f4*4+2][o] = w.z; Aq[f4*4+3][o] = w.w;
            w = *(const float4*)&Wk[(size_t)(o0+o)*CC + kc + f4*4];
            Ak[f4*4+0][o] = w.x; Ak[f4*4+1][o] = w.y; Ak[f4*4+2][o] = w.z; Ak[f4*4+3][o] = w.w;
            w = *(const float4*)&Wv[(size_t)(o0+o)*CC + kc + f4*4];
            Av[f4*4+0][o] = w.x; Av[f4*4+1][o] = w.y; Av[f4*4+2][o] = w.z; Av[f4*4+3][o] = w.w;
        }
        {
            int r = tid >> 4, c4 = tid & 15;
            *(float4*)&Bs[r][c4*4] = *(const float4*)&Hb[(size_t)(kc+r)*NN + n0 + c4*4];
        }
        __syncthreads();
        #pragma unroll
        for (int kk = 0; kk < 16; kk++) {
            float bb[4], a[4];
            *(float4*)bb = *(const float4*)&Bs[kk][tx*4];
            *(float4*)a = *(const float4*)&Aq[kk][ty*4];
            #pragma unroll
            for (int i = 0; i < 4; i++)
                #pragma unroll
                for (int j = 0; j < 4; j++) aq[i][j] = fmaf(a[i], bb[j], aq[i][j]);
            *(float4*)a = *(const float4*)&Ak[kk][ty*4];
            #pragma unroll
            for (int i = 0; i < 4; i++)
                #pragma unroll
                for (int j = 0; j < 4; j++) ak[i][j] = fmaf(a[i], bb[j], ak[i][j]);
            *(float4*)a = *(const float4*)&Av[kk][ty*4];
            #pragma unroll
            for (int i = 0; i < 4; i++)
                #pragma unroll
                for (int j = 0; j < 4; j++) av[i][j] = fmaf(a[i], bb[j], av[i][j]);
        }
        __syncthreads();
    }

    const float scale = 0.08838834764831843f;  // 128^-0.5
    // K: [c][n] layout, rows of n
    #pragma unroll
    for (int i = 0; i < 4; i++) {
        const int o = o0 + ty*4 + i;
        const float bi = bk[o];
        __nv_bfloat16* kp = g_kb + (size_t)b*CC*NN + (size_t)o*NN + n0 + tx*4;
        __nv_bfloat162 p0 = __float22bfloat162_rn(make_float2(ak[i][0]+bi, ak[i][1]+bi));
        __nv_bfloat162 p1 = __float22bfloat162_rn(make_float2(ak[i][2]+bi, ak[i][3]+bi));
        *(__nv_bfloat162*)(kp)   = p0;
        *(__nv_bfloat162*)(kp+2) = p1;
    }
    // Q^T and V^T: [n][c] layout, rows of c
    #pragma unroll
    for (int j = 0; j < 4; j++) {
        const int n = n0 + tx*4 + j;
        {
            __nv_bfloat16* qp = g_qt + (size_t)b*NN*CC + (size_t)n*CC + o0 + ty*4;
            float q0 = (aq[0][j] + bq[o0+ty*4+0]) * scale;
            float q1 = (aq[1][j] + bq[o0+ty*4+1]) * scale;
            float q2 = (aq[2][j] + bq[o0+ty*4+2]) * scale;
            float q3 = (aq[3][j] + bq[o0+ty*4+3]) * scale;
            *(__nv_bfloat162*)(qp)   = __float22bfloat162_rn(make_float2(q0, q1));
            *(__nv_bfloat162*)(qp+2) = __float22bfloat162_rn(make_float2(q2, q3));
        }
        {
            __nv_bfloat16* vp = g_vt + (size_t)b*NN*CC + (size_t)n*CC + o0 + ty*4;
            float v0 = av[0][j] + bv[o0+ty*4+0];
            float v1 = av[1][j] + bv[o0+ty*4+1];
            float v2 = av[2][j] + bv[o0+ty*4+2];
            float v3 = av[3][j] + bv[o0+ty*4+3];
            *(__nv_bfloat162*)(vp)   = __float22bfloat162_rn(make_float2(v0, v1));
            *(__nv_bfloat162*)(vp+2) = __float22bfloat162_rn(make_float2(v2, v3));
        }
    }
}

// ---------------------------------------------------------------------------
// mma.sync helpers
// ---------------------------------------------------------------------------
__device__ __forceinline__ void ldsm_x4(uint32_t& r0, uint32_t& r1, uint32_t& r2,
                                        uint32_t& r3, const void* p) {
    uint32_t addr = (uint32_t)__cvta_generic_to_shared(p);
    asm volatile("ldmatrix.sync.aligned.m8n8.x4.shared.b16 {%0,%1,%2,%3}, [%4];"
                 : "=r"(r0), "=r"(r1), "=r"(r2), "=r"(r3) : "r"(addr));
}
__device__ __forceinline__ void ldsm_x4_t(uint32_t& r0, uint32_t& r1, uint32_t& r2,
                                          uint32_t& r3, const void* p) {
    uint32_t addr = (uint32_t)__cvta_generic_to_shared(p);
    asm volatile("ldmatrix.sync.aligned.m8n8.x4.trans.shared.b16 {%0,%1,%2,%3}, [%4];"
                 : "=r"(r0), "=r"(r1), "=r"(r2), "=r"(r3) : "r"(addr));
}
__device__ __forceinline__ void mma_bf16(float* c, const uint32_t* a, const uint32_t* b) {
    asm volatile(
        "mma.sync.aligned.m16n8k16.row.col.f32.bf16.bf16.f32 "
        "{%0,%1,%2,%3},{%4,%5,%6,%7},{%8,%9},{%0,%1,%2,%3};"
        : "+f"(c[0]), "+f"(c[1]), "+f"(c[2]), "+f"(c[3])
        : "r"(a[0]), "r"(a[1]), "r"(a[2]), "r"(a[3]), "r"(b[0]), "r"(b[1]));
}

// ---------------------------------------------------------------------------
// QK^T: S[n][m] = sum_c qt[n][c] * k[c][m], bf16 in, bf16 out, fp32 accum.
// BM=BN=128, BK=32, 8 warps (4 row x 2 col), warp tile 32x64.
// ---------------------------------------------------------------------------
__global__ __launch_bounds__(256, 2) void qk_mma_kernel() {
    const int b  = blockIdx.z;
    const int n0 = blockIdx.x * 128;
    const int m0 = blockIdx.y * 128;
    const __nv_bfloat16* Ag = g_qt + (size_t)b*NN*CC;   // [n][c]
    const __nv_bfloat16* Bg = g_kb + (size_t)b*CC*NN;   // [c][m]
    __nv_bfloat16* S = g_S + (size_t)b*NN*NN;

    __shared__ __align__(16) __nv_bfloat16 As[128][40];
    __shared__ __align__(16) __nv_bfloat16 Bs[32][136];
    const int tid = threadIdx.x;
    const int lane = tid & 31, wid = tid >> 5;
    const int wr = wid & 3, wc = wid >> 2;

    float acc[2][8][4] = {};

    for (int kc = 0; kc < CC; kc += 32) {
        #pragma unroll
        for (int i = 0; i < 2; i++) {
            int id = tid + i*256;
            int r = id >> 2, ch = id & 3;
            *(uint4*)&As[r][ch*8] = *(const uint4*)&Ag[(size_t)(n0+r)*CC + kc + ch*8];
        }
        #pragma unroll
        for (int i = 0; i < 2; i++) {
            int id = tid + i*256;
            int r = id >> 4, ch = id & 15;
            *(uint4*)&Bs[r][ch*8] = *(const uint4*)&Bg[(size_t)(kc+r)*NN + m0 + ch*8];
        }
        __syncthreads();
        #pragma unroll
        for (int kk = 0; kk < 32; kk += 16) {
            uint32_t a[2][4], bf[8][2];
            #pragma unroll
            for (int mi = 0; mi < 2; mi++)
                ldsm_x4(a[mi][0], a[mi][1], a[mi][2], a[mi][3],
                        &As[wr*32 + mi*16 + (lane & 15)][kk + (lane >> 4)*8]);
            #pragma unroll
            for (int bj = 0; bj < 4; bj++) {
                uint32_t r0, r1, r2, r3;
                ldsm_x4_t(r0, r1, r2, r3,
                          &Bs[kk + (lane & 15)][wc*64 + bj*16 + (lane >> 4)*8]);
                bf[2*bj][0] = r0; bf[2*bj][1] = r1;
                bf[2*bj+1][0] = r2; bf[2*bj+1][1] = r3;
            }
            #pragma unroll
            for (int mi = 0; mi < 2; mi++)
                #pragma unroll
                for (int cj = 0; cj < 8; cj++)
                    mma_bf16(acc[mi][cj], a[mi], bf[cj]);
        }
        __syncthreads();
    }

    #pragma unroll
    for (int mi = 0; mi < 2; mi++) {
        int r0 = n0 + wr*32 + mi*16 + (lane >> 2);
        #pragma unroll
        for (int cj = 0; cj < 8; cj++) {
            int c = m0 + wc*64 + cj*8 + (lane & 3)*2;
            float* a = acc[mi][cj];
            *(__nv_bfloat162*)&S[(size_t)r0*NN + c] =
                __float22bfloat162_rn(make_float2(a[0], a[1]));
            *(__nv_bfloat162*)&S[(size_t)(r0+8)*NN + c] =
                __float22bfloat162_rn(make_float2(a[2], a[3]));
        }
    }
}

// ---------------------------------------------------------------------------
// Fast exp via FMA pipe. Valid for x <= 0.
// ---------------------------------------------------------------------------
__device__ __forceinline__ float fast_exp(float x) {
    float t = fmaxf(x * 1.44269504088896341f, -126.0f);
    float fi = floorf(t);
    float p = (t - fi) * 0.69314718055994531f;
    float r = 1.3888888888888889e-3f;
    r = fmaf(r, p, 8.3333333333333333e-3f);
    r = fmaf(r, p, 4.1666666666666664e-2f);
    r = fmaf(r, p, 1.6666666666666666e-1f);
    r = fmaf(r, p, 0.5f);
    r = fmaf(r, p, 1.0f);
    r = fmaf(r, p, 1.0f);
    float sc = __int_as_float(((int)fi + 127) << 23);
    return r * sc;
}

__device__ __forceinline__ void unpack8(uint4 u, float* f) {
    const uint32_t w[4] = {u.x, u.y, u.z, u.w};
    #pragma unroll
    for (int i = 0; i < 4; i++) {
        float2 p = __bfloat1622float2(*(const __nv_bfloat162*)&w[i]);
        f[2*i] = p.x; f[2*i+1] = p.y;
    }
}
__device__ __forceinline__ uint4 pack8(const float* f) {
    uint4 u;
    uint32_t w[4];
    #pragma unroll
    for (int i = 0; i < 4; i++) {
        __nv_bfloat162 p = __float22bfloat162_rn(make_float2(f[2*i], f[2*i+1]));
        w[i] = *(uint32_t*)&p;
    }
    u.x = w[0]; u.y = w[1]; u.z = w[2]; u.w = w[3];
    return u;
}

// ---------------------------------------------------------------------------
// Row softmax over 4096 bf16 entries, in place.
// ---------------------------------------------------------------------------
__global__ void softmax_kernel() {
    uint4* row = (uint4*)(g_S + (size_t)blockIdx.x * NN);
    const int tid = threadIdx.x;
    __shared__ float sh[8];

    float v[16];
    uint4 r0 = row[tid], r1 = row[tid + 256];
    unpack8(r0, v); unpack8(r1, v + 8);

    float mx = -3.0e38f;
    #pragma unroll
    for (int i = 0; i < 16; i++) mx = fmaxf(mx, v[i]);
    #pragma unroll
    for (int o = 16; o; o >>= 1) mx = fmaxf(mx, __shfl_xor_sync(0xffffffffu, mx, o));
    if ((tid & 31) == 0) sh[tid >> 5] = mx;
    __syncthreads();
    mx = sh[0];
    #pragma unroll
    for (int i = 1; i < 8; i++) mx = fmaxf(mx, sh[i]);
    __syncthreads();

    float sum = 0.f;
    #pragma unroll
    for (int i = 0; i < 16; i++) { v[i] = fast_exp(v[i] - mx); sum += v[i]; }
    #pragma unroll
    for (int o = 16; o; o >>= 1) sum += __shfl_xor_sync(0xffffffffu, sum, o);
    if ((tid & 31) == 0) sh[tid >> 5] = sum;
    __syncthreads();
    float tot = 0.f;
    #pragma unroll
    for (int i = 0; i < 8; i++) tot += sh[i];
    const float inv = 1.0f / tot;
    #pragma unroll
    for (int i = 0; i < 16; i++) v[i] *= inv;

    row[tid] = pack8(v);
    row[tid + 256] = pack8(v + 8);
}

// ---------------------------------------------------------------------------
// PV: O[n][c] = sum_m P[n][m] * vt[m][c]. Split-K x4, fp32 partials.
// Same MMA structure as QK.
// ---------------------------------------------------------------------------
__global__ __launch_bounds__(256, 2) void pv_mma_kernel() {
    const int b  = blockIdx.z;
    const int n0 = blockIdx.x * 128;
    const int ks = blockIdx.y;
    const int mbase = ks * (NN / KSLICES);
    const __nv_bfloat16* Ag = g_S  + (size_t)b*NN*NN;   // P [n][m]
    const __nv_bfloat16* Bg = g_vt + (size_t)b*NN*CC;   // vt [m][c]
    float* O = g_opart + ((size_t)(ks*BB + b))*NN*CC;

    __shared__ __align__(16) __nv_bfloat16 As[128][40];
    __shared__ __align__(16) __nv_bfloat16 Bs[32][136];
    const int tid = threadIdx.x;
    const int lane = tid & 31, wid = tid >> 5;
    const int wr = wid & 3, wc = wid >> 2;

    float acc[2][8][4] = {};

    for (int kc = 0; kc < NN/KSLICES; kc += 32) {
        #pragma unroll
        for (int i = 0; i < 2; i++) {
            int id = tid + i*256;
            int r = id >> 2, ch = id & 3;
            *(uint4*)&As[r][ch*8] =
                *(const uint4*)&Ag[(size_t)(n0+r)*NN + mbase + kc + ch*8];
        }
        #pragma unroll
        for (int i = 0; i < 2; i++) {
            int id = tid + i*256;
            int r = id >> 4, ch = id & 15;
            *(uint4*)&Bs[r][ch*8] =
                *(const uint4*)&Bg[(size_t)(mbase+kc+r)*CC + ch*8];
        }
        __syncthreads();
        #pragma unroll
        for (int kk = 0; kk < 32; kk += 16) {
            uint32_t a[2][4], bf[8][2];
            #pragma unroll
            for (int mi = 0; mi < 2; mi++)
                ldsm_x4(a[mi][0], a[mi][1], a[mi][2], a[mi][3],
                        &As[wr*32 + mi*16 + (lane & 15)][kk + (lane >> 4)*8]);
            #pragma unroll
            for (int bj = 0; bj < 4; bj++) {
                uint32_t r0, r1, r2, r3;
                ldsm_x4_t(r0, r1, r2, r3,
                          &Bs[kk + (lane & 15)][wc*64 + bj*16 + (lane >> 4)*8]);
                bf[2*bj][0] = r0; bf[2*bj][1] = r1;
                bf[2*bj+1][0] = r2; bf[2*bj+1][1] = r3;
            }
            #pragma unroll
            for (int mi = 0; mi < 2; mi++)
                #pragma unroll
                for (int cj = 0; cj < 8; cj++)
                    mma_bf16(acc[mi][cj], a[mi], bf[cj]);
        }
        __syncthreads();
    }

    #pragma unroll
    for (int mi = 0; mi < 2; mi++) {
        int r0 = n0 + wr*32 + mi*16 + (lane >> 2);
        #pragma unroll
        for (int cj = 0; cj < 8; cj++) {
            int c = wc*64 + cj*8 + (lane & 3)*2;
            float* a = acc[mi][cj];
            *(float2*)&O[(size_t)r0*CC + c]     = make_float2(a[0], a[1]);
            *(float2*)&O[(size_t)(r0+8)*CC + c] = make_float2(a[2], a[3]);
        }
    }
}

// Sum the KSLICES partial O buffers -> g_ot [b][n][c].
__global__ void reduce_o_kernel() {
    const size_t i = ((size_t)blockIdx.x*256 + threadIdx.x) * 4;
    const size_t stride = (size_t)BB*NN*CC;
    float4 a = *(const float4*)&g_opart[i];
    #pragma unroll
    for (int s = 1; s < KSLICES; s++) {
        float4 p = *(const float4*)&g_opart[s*stride + i];
        a.x += p.x; a.y += p.y; a.z += p.z; a.w += p.w;
    }
    *(float4*)&g_ot[i] = a;
}

// ---------------------------------------------------------------------------
// Proj conv: out[o][n] = sum_c Wp[o][c] * ot[n][c] + bp[o] + x[o][n]
// Input is [n][c] (transposed), tile-transposed through smem.
// ---------------------------------------------------------------------------
__global__ __launch_bounds__(256) void proj_kernel(
    const float* __restrict__ W, const float* __restrict__ bias,
    const float* __restrict__ resid, float* __restrict__ out)
{
    const int b  = blockIdx.z;
    const int n0 = blockIdx.x * 64;
    const int o0 = blockIdx.y * 64;
    const float* Ht = g_ot + (size_t)b*NN*CC;  // [n][c]

    __shared__ __align__(16) float As[16][68];
    __shared__ __align__(16) float Bs[16][68];
    const int tid = threadIdx.x;
    const int tx = tid & 15, ty = tid >> 4;
    float acc[4][4] = {};

    for (int kc = 0; kc < CC; kc += 16) {
        {
            int o = tid >> 2, f4 = tid & 3;
            float4 w = *(const float4*)&W[(size_t)(o0+o)*CC + kc + f4*4];
            As[f4*4+0][o] = w.x; As[f4*4+1][o] = w.y;
            As[f4*4+2][o] = w.z; As[f4*4+3][o] = w.w;
        }
        {
            int np = tid >> 2, c4 = tid & 3;
            float4 v = *(const float4*)&Ht[(size_t)(n0+np)*CC + kc + c4*4];
            Bs[c4*4+0][np] = v.x; Bs[c4*4+1][np] = v.y;
            Bs[c4*4+2][np] = v.z; Bs[c4*4+3][np] = v.w;
        }
        __syncthreads();
        #pragma unroll
        for (int kk = 0; kk < 16; kk++) {
            float a[4], bb[4];
            *(float4*)a  = *(const float4*)&As[kk][ty*4];
            *(float4*)bb = *(const float4*)&Bs[kk][tx*4];
            #pragma unroll
            for (int i = 0; i < 4; i++)
                #pragma unroll
                for (int j = 0; j < 4; j++)
                    acc[i][j] = fmaf(a[i], bb[j], acc[i][j]);
        }
        __syncthreads();
    }

    const size_t ob = (size_t)b*CC*NN;
    #pragma unroll
    for (int i = 0; i < 4; i++) {
        const int o = o0 + ty*4 + i;
        const float bi = bias[o];
        const size_t rowoff = ob + (size_t)o*NN + n0 + tx*4;
        float4 r4 = *(const float4*)&resid[rowoff];
        float4 v;
        v.x = acc[i][0] + bi + r4.x; v.y = acc[i][1] + bi + r4.y;
        v.z = acc[i][2] + bi + r4.z; v.w = acc[i][3] + bi + r4.w;
        *(float4*)&out[rowoff] = v;
    }
}

// ---------------------------------------------------------------------------
extern "C" void kernel_launch(void* const* d_in, const int* in_sizes, int n_in,
                              void* d_out, int out_size) {
    const float* x   = (const float*)d_in[0];
    const float* gnw = (const float*)d_in[1];
    const float* gnb = (const float*)d_in[2];
    const float* wq  = (const float*)d_in[3];
    const float* bq  = (const float*)d_in[4];
    const float* wk  = (const float*)d_in[5];
    const float* bk  = (const float*)d_in[6];
    const float* wv  = (const float*)d_in[7];
    const float* bv  = (const float*)d_in[8];
    const float* wp  = (const float*)d_in[9];
    const float* bp  = (const float*)d_in[10];
    float* out = (float*)d_out;

    gn_kernel<<<BB*NG, 256>>>(x, gnw, gnb);

    dim3 cg(NN/64, CC/64, BB);
    conv_qkv_kernel<<<cg, 256>>>(wq, bq, wk, bk, wv, bv);

    dim3 sg(NN/128, NN/128, BB);
    qk_mma_kernel<<<sg, 256>>>();

    softmax_kernel<<<BB*NN, 256>>>();

    dim3 pg(NN/128, KSLICES, BB);
    pv_mma_kernel<<<pg, 256>>>();
    reduce_o_kernel<<<(BB*NN*CC)/1024, 256>>>();

    proj_kernel<<<cg, 256>>>(wp, bp, x, out);
}

// round 3
// speedup vs baseline: 3.7633x; 1.1497x over previous
#include <cuda_runtime.h>
#include <cuda_bf16.h>
#include <math.h>
#include <stdint.h>

#define BB 2
#define CC 128
#define NN 4096
#define NG 32
#define CPG 4

#define MBLK 64          // query rows per CTA
#define KT   64          // keys per tile
#define PAD  8
#define LDK  (CC + PAD)  // 136 bf16 per smem row

// ---------------- scratch (static device globals) ----------------
__device__ float          g_h[BB*CC*NN];     // GN output [b][c][n] fp32
__device__ __nv_bfloat16  g_qt[BB*NN*CC];    // Q^T [b][n][c] bf16 (scale folded)
__device__ __nv_bfloat16  g_kt[BB*NN*CC];    // K^T [b][n][c] bf16
__device__ __nv_bfloat16  g_vt[BB*NN*CC];    // V^T [b][n][c] bf16
__device__ float          g_ot[BB*NN*CC];    // attention out [b][n][c] fp32

// ---------------------------------------------------------------------------
// GroupNorm
// ---------------------------------------------------------------------------
__global__ void gn_kernel(const float* __restrict__ x,
                          const float* __restrict__ gamma,
                          const float* __restrict__ beta) {
    const int bg = blockIdx.x;
    const int b = bg / NG, g = bg % NG;
    const size_t base = ((size_t)b*CC + g*CPG) * NN;
    const float* xp = x + base;
    const int M = CPG*NN;

    float s = 0.f, s2 = 0.f;
    for (int i = threadIdx.x; i < M; i += 256) {
        float v = xp[i]; s += v; s2 += v*v;
    }
    __shared__ float sh0[8], sh1[8];
    #pragma unroll
    for (int o = 16; o; o >>= 1) {
        s  += __shfl_xor_sync(0xffffffffu, s,  o);
        s2 += __shfl_xor_sync(0xffffffffu, s2, o);
    }
    if ((threadIdx.x & 31) == 0) { sh0[threadIdx.x>>5] = s; sh1[threadIdx.x>>5] = s2; }
    __syncthreads();
    float ts = 0.f, ts2 = 0.f;
    #pragma unroll
    for (int i = 0; i < 8; i++) { ts += sh0[i]; ts2 += sh1[i]; }
    const float mean = ts / (float)M;
    const float var  = ts2 / (float)M - mean*mean;
    const float inv  = rsqrtf(var + 1e-5f);

    float* hp = g_h + base;
    for (int i = threadIdx.x; i < M; i += 256) {
        int c = g*CPG + (i >> 12);
        hp[i] = (xp[i] - mean) * inv * gamma[c] + beta[c];
    }
}

// ---------------------------------------------------------------------------
// Fused QKV 1x1 convs -> q/k/v all in [n][c] bf16 (q scaled by C^-0.5).
// ---------------------------------------------------------------------------
__global__ __launch_bounds__(256) void conv_qkv_kernel(
    const float* __restrict__ Wq, const float* __restrict__ bq,
    const float* __restrict__ Wk, const float* __restrict__ bk,
    const float* __restrict__ Wv, const float* __restrict__ bv)
{
    const int b  = blockIdx.z;
    const int n0 = blockIdx.x * 64;
    const int o0 = blockIdx.y * 64;
    const float* Hb = g_h + (size_t)b*CC*NN;

    __shared__ __align__(16) float Aq[16][68], Ak[16][68], Av[16][68];
    __shared__ __align__(16) float Bs[16][64];
    const int tid = threadIdx.x;
    const int tx = tid & 15, ty = tid >> 4;
    float aq[4][4] = {}, ak[4][4] = {}, av[4][4] = {};

    for (int kc = 0; kc < CC; kc += 16) {
        {
            int o = tid >> 2, f4 = tid & 3;
            float4 w;
            w = *(const float4*)&Wq[(size_t)(o0+o)*CC + kc + f4*4];
            Aq[f4*4+0][o] = w.x; Aq[f4*4+1][o] = w.y; Aq[f4*4+2][o] = w.z; Aq[f4*4+3][o] = w.w;
            w = *(const float4*)&Wk[(size_t)(o0+o)*CC + kc + f4*4];
            Ak[f4*4+0][o] = w.x; Ak[f4*4+1][o] = w.y; Ak[f4*4+2][o] = w.z; Ak[f4*4+3][o] = w.w;
            w = *(const float4*)&Wv[(size_t)(o0+o)*CC + kc + f4*4];
            Av[f4*4+0][o] = w.x; Av[f4*4+1][o] = w.y; Av[f4*4+2][o] = w.z; Av[f4*4+3][o] = w.w;
        }
        {
            int r = tid >> 4, c4 = tid & 15;
            *(float4*)&Bs[r][c4*4] = *(const float4*)&Hb[(size_t)(kc+r)*NN + n0 + c4*4];
        }
        __syncthreads();
        #pragma unroll
        for (int kk = 0; kk < 16; kk++) {
            float bb[4], a[4];
            *(float4*)bb = *(const float4*)&Bs[kk][tx*4];
            *(float4*)a = *(const float4*)&Aq[kk][ty*4];
            #pragma unroll
            for (int i = 0; i < 4; i++)
                #pragma unroll
                for (int j = 0; j < 4; j++) aq[i][j] = fmaf(a[i], bb[j], aq[i][j]);
            *(float4*)a = *(const float4*)&Ak[kk][ty*4];
            #pragma unroll
            for (int i = 0; i < 4; i++)
                #pragma unroll
                for (int j = 0; j < 4; j++) ak[i][j] = fmaf(a[i], bb[j], ak[i][j]);
            *(float4*)a = *(const float4*)&Av[kk][ty*4];
            #pragma unroll
            for (int i = 0; i < 4; i++)
                #pragma unroll
                for (int j = 0; j < 4; j++) av[i][j] = fmaf(a[i], bb[j], av[i][j]);
        }
        __syncthreads();
    }

    const float scale = 0.08838834764831843f;  // 128^-0.5
    #pragma unroll
    for (int j = 0; j < 4; j++) {
        const int n = n0 + tx*4 + j;
        const size_t rowbase = (size_t)b*NN*CC + (size_t)n*CC + o0 + ty*4;
        {
            float q0 = (aq[0][j] + bq[o0+ty*4+0]) * scale;
            float q1 = (aq[1][j] + bq[o0+ty*4+1]) * scale;
            float q2 = (aq[2][j] + bq[o0+ty*4+2]) * scale;
            float q3 = (aq[3][j] + bq[o0+ty*4+3]) * scale;
            __nv_bfloat16* qp = g_qt + rowbase;
            *(__nv_bfloat162*)(qp)   = __float22bfloat162_rn(make_float2(q0, q1));
            *(__nv_bfloat162*)(qp+2) = __float22bfloat162_rn(make_float2(q2, q3));
        }
        {
            float k0 = ak[0][j] + bk[o0+ty*4+0];
            float k1 = ak[1][j] + bk[o0+ty*4+1];
            float k2 = ak[2][j] + bk[o0+ty*4+2];
            float k3 = ak[3][j] + bk[o0+ty*4+3];
            __nv_bfloat16* kp = g_kt + rowbase;
            *(__nv_bfloat162*)(kp)   = __float22bfloat162_rn(make_float2(k0, k1));
            *(__nv_bfloat162*)(kp+2) = __float22bfloat162_rn(make_float2(k2, k3));
        }
        {
            float v0 = av[0][j] + bv[o0+ty*4+0];
            float v1 = av[1][j] + bv[o0+ty*4+1];
            float v2 = av[2][j] + bv[o0+ty*4+2];
            float v3 = av[3][j] + bv[o0+ty*4+3];
            __nv_bfloat16* vp = g_vt + rowbase;
            *(__nv_bfloat162*)(vp)   = __float22bfloat162_rn(make_float2(v0, v1));
            *(__nv_bfloat162*)(vp+2) = __float22bfloat162_rn(make_float2(v2, v3));
        }
    }
}

// ---------------------------------------------------------------------------
// mma / ldmatrix / cp.async helpers
// ---------------------------------------------------------------------------
__device__ __forceinline__ void ldsm_x4(uint32_t& r0, uint32_t& r1, uint32_t& r2,
                                        uint32_t& r3, const void* p) {
    uint32_t addr = (uint32_t)__cvta_generic_to_shared(p);
    asm volatile("ldmatrix.sync.aligned.m8n8.x4.shared.b16 {%0,%1,%2,%3}, [%4];"
                 : "=r"(r0), "=r"(r1), "=r"(r2), "=r"(r3) : "r"(addr));
}
__device__ __forceinline__ void ldsm_x4_t(uint32_t& r0, uint32_t& r1, uint32_t& r2,
                                          uint32_t& r3, const void* p) {
    uint32_t addr = (uint32_t)__cvta_generic_to_shared(p);
    asm volatile("ldmatrix.sync.aligned.m8n8.x4.trans.shared.b16 {%0,%1,%2,%3}, [%4];"
                 : "=r"(r0), "=r"(r1), "=r"(r2), "=r"(r3) : "r"(addr));
}
__device__ __forceinline__ void mma_bf16(float* c, const uint32_t* a, const uint32_t* b) {
    asm volatile(
        "mma.sync.aligned.m16n8k16.row.col.f32.bf16.bf16.f32 "
        "{%0,%1,%2,%3},{%4,%5,%6,%7},{%8,%9},{%0,%1,%2,%3};"
        : "+f"(c[0]), "+f"(c[1]), "+f"(c[2]), "+f"(c[3])
        : "r"(a[0]), "r"(a[1]), "r"(a[2]), "r"(a[3]), "r"(b[0]), "r"(b[1]));
}
__device__ __forceinline__ void cp_async16(void* smem, const void* gmem) {
    uint32_t s = (uint32_t)__cvta_generic_to_shared(smem);
    asm volatile("cp.async.cg.shared.global [%0], [%1], 16;" :: "r"(s), "l"(gmem));
}
__device__ __forceinline__ void cp_commit() {
    asm volatile("cp.async.commit_group;");
}
__device__ __forceinline__ void cp_wait_all() {
    asm volatile("cp.async.wait_group 0;");
}

__device__ __forceinline__ float fast_exp(float x) {
    float t = fmaxf(x * 1.44269504088896341f, -126.0f);
    float fi = floorf(t);
    float p = (t - fi) * 0.69314718055994531f;
    float r = 1.3888888888888889e-3f;
    r = fmaf(r, p, 8.3333333333333333e-3f);
    r = fmaf(r, p, 4.1666666666666664e-2f);
    r = fmaf(r, p, 1.6666666666666666e-1f);
    r = fmaf(r, p, 0.5f);
    r = fmaf(r, p, 1.0f);
    r = fmaf(r, p, 1.0f);
    float sc = __int_as_float(((int)fi + 127) << 23);
    return r * sc;
}
__device__ __forceinline__ uint32_t packbf2(float a, float b) {
    __nv_bfloat162 p = __float22bfloat162_rn(make_float2(a, b));
    return *(uint32_t*)&p;
}

// ---------------------------------------------------------------------------
// Fused flash attention: O[n][c] = softmax(Q K^T) V, all inputs [n][c] bf16.
// 128 threads (4 warps), 64 query rows per CTA (16 per warp), KT=64 key tiles,
// cp.async double-buffered K/V, online softmax.
// ---------------------------------------------------------------------------
__global__ __launch_bounds__(128, 2) void flash_kernel() {
    extern __shared__ __align__(16) __nv_bfloat16 sm[];
    __nv_bfloat16* Qs = sm;                  // [64][LDK]
    __nv_bfloat16* Ks = sm + MBLK*LDK;       // [2][64][LDK]
    __nv_bfloat16* Vs = sm + 3*MBLK*LDK;     // [2][64][LDK]

    const int b  = blockIdx.y;
    const int n0 = blockIdx.x * MBLK;
    const __nv_bfloat16* Qg = g_qt + (size_t)b*NN*CC;
    const __nv_bfloat16* Kg = g_kt + (size_t)b*NN*CC;
    const __nv_bfloat16* Vg = g_vt + (size_t)b*NN*CC;

    const int tid = threadIdx.x;
    const int lane = tid & 31, w = tid >> 5;

    // ---- load Q tile (plain loads) + prologue cp.async of KV tile 0 ----
    #pragma unroll
    for (int i = 0; i < 8; i++) {
        int id = tid + i*128;            // 1024 chunks of 8 bf16
        int r = id >> 4, ch = id & 15;
        *(uint4*)&Qs[r*LDK + ch*8] = *(const uint4*)&Qg[(size_t)(n0+r)*CC + ch*8];
    }
    #pragma unroll
    for (int i = 0; i < 8; i++) {
        int id = tid + i*128;
        int r = id >> 4, ch = id & 15;
        cp_async16(&Ks[r*LDK + ch*8], &Kg[(size_t)r*CC + ch*8]);
        cp_async16(&Vs[r*LDK + ch*8], &Vg[(size_t)r*CC + ch*8]);
    }
    cp_commit();
    __syncthreads();

    // ---- persistent Q fragments ----
    uint32_t qf[8][4];
    #pragma unroll
    for (int kk = 0; kk < 8; kk++)
        ldsm_x4(qf[kk][0], qf[kk][1], qf[kk][2], qf[kk][3],
                &Qs[(w*16 + (lane & 15))*LDK + kk*16 + (lane >> 4)*8]);

    float oacc[16][4] = {};
    float m0 = -1e30f, m1 = -1e30f, s0 = 0.f, s1 = 0.f;

    const int NITER = NN / KT;  // 64
    for (int it = 0; it < NITER; it++) {
        cp_wait_all();
        __syncthreads();

        // prefetch next KV tile into the other buffer
        if (it + 1 < NITER) {
            const int nb = (it + 1) & 1;
            const size_t kbase = (size_t)(it + 1) * KT * CC;
            __nv_bfloat16* Kd = Ks + nb*MBLK*LDK;
            __nv_bfloat16* Vd = Vs + nb*MBLK*LDK;
            #pragma unroll
            for (int i = 0; i < 8; i++) {
                int id = tid + i*128;
                int r = id >> 4, ch = id & 15;
                cp_async16(&Kd[r*LDK + ch*8], &Kg[kbase + (size_t)r*CC + ch*8]);
                cp_async16(&Vd[r*LDK + ch*8], &Vg[kbase + (size_t)r*CC + ch*8]);
            }
        }
        cp_commit();

        const __nv_bfloat16* Kb = Ks + (it & 1)*MBLK*LDK;
        const __nv_bfloat16* Vb = Vs + (it & 1)*MBLK*LDK;

        // ---- S = Q K^T  (16 x 64 per warp) ----
        float sacc[8][4] = {};
        #pragma unroll
        for (int kk = 0; kk < 8; kk++) {
            #pragma unroll
            for (int t16 = 0; t16 < 4; t16++) {
                uint32_t r0, r1, r2, r3;
                ldsm_x4(r0, r1, r2, r3,
                        &Kb[(t16*16 + (lane & 15))*LDK + kk*16 + (lane >> 4)*8]);
                uint32_t bf0[2] = {r0, r2}, bf1[2] = {r1, r3};
                mma_bf16(sacc[2*t16],   qf[kk], bf0);
                mma_bf16(sacc[2*t16+1], qf[kk], bf1);
            }
        }

        // ---- online softmax update ----
        float mx0 = -1e30f, mx1 = -1e30f;
        #pragma unroll
        for (int j = 0; j < 8; j++) {
            mx0 = fmaxf(mx0, fmaxf(sacc[j][0], sacc[j][1]));
            mx1 = fmaxf(mx1, fmaxf(sacc[j][2], sacc[j][3]));
        }
        mx0 = fmaxf(mx0, __shfl_xor_sync(0xffffffffu, mx0, 1));
        mx0 = fmaxf(mx0, __shfl_xor_sync(0xffffffffu, mx0, 2));
        mx1 = fmaxf(mx1, __shfl_xor_sync(0xffffffffu, mx1, 1));
        mx1 = fmaxf(mx1, __shfl_xor_sync(0xffffffffu, mx1, 2));

        const float mn0 = fmaxf(m0, mx0), mn1 = fmaxf(m1, mx1);
        const float sf0 = fast_exp(m0 - mn0), sf1 = fast_exp(m1 - mn1);
        m0 = mn0; m1 = mn1;

        float rs0 = 0.f, rs1 = 0.f;
        uint32_t pf[4][4];
        #pragma unroll
        for (int t16 = 0; t16 < 4; t16++) {
            float p00 = fast_exp(sacc[2*t16][0]   - mn0);
            float p01 = fast_exp(sacc[2*t16][1]   - mn0);
            float p02 = fast_exp(sacc[2*t16][2]   - mn1);
            float p03 = fast_exp(sacc[2*t16][3]   - mn1);
            float p10 = fast_exp(sacc[2*t16+1][0] - mn0);
            float p11 = fast_exp(sacc[2*t16+1][1] - mn0);
            float p12 = fast_exp(sacc[2*t16+1][2] - mn1);
            float p13 = fast_exp(sacc[2*t16+1][3] - mn1);
            rs0 += (p00 + p01) + (p10 + p11);
            rs1 += (p02 + p03) + (p12 + p13);
            pf[t16][0] = packbf2(p00, p01);
            pf[t16][1] = packbf2(p02, p03);
            pf[t16][2] = packbf2(p10, p11);
            pf[t16][3] = packbf2(p12, p13);
        }
        rs0 += __shfl_xor_sync(0xffffffffu, rs0, 1);
        rs0 += __shfl_xor_sync(0xffffffffu, rs0, 2);
        rs1 += __shfl_xor_sync(0xffffffffu, rs1, 1);
        rs1 += __shfl_xor_sync(0xffffffffu, rs1, 2);
        s0 = s0*sf0 + rs0;
        s1 = s1*sf1 + rs1;

        #pragma unroll
        for (int t = 0; t < 16; t++) {
            oacc[t][0] *= sf0; oacc[t][1] *= sf0;
            oacc[t][2] *= sf1; oacc[t][3] *= sf1;
        }

        // ---- O += P V  (16 x 128 per warp) ----
        #pragma unroll
        for (int kv = 0; kv < 4; kv++) {
            #pragma unroll
            for (int cb = 0; cb < 8; cb++) {
                uint32_t r0, r1, r2, r3;
                ldsm_x4_t(r0, r1, r2, r3,
                          &Vb[(kv*16 + (lane & 15))*LDK + cb*16 + (lane >> 4)*8]);
                uint32_t bf0[2] = {r0, r1}, bf1[2] = {r2, r3};
                mma_bf16(oacc[2*cb],   pf[kv], bf0);
                mma_bf16(oacc[2*cb+1], pf[kv], bf1);
            }
        }
        __syncthreads();
    }

    // ---- epilogue ----
    const float inv0 = 1.0f / s0, inv1 = 1.0f / s1;
    const int r = n0 + w*16 + (lane >> 2);
    float* Ob = g_ot + (size_t)b*NN*CC;
    #pragma unroll
    for (int cb = 0; cb < 16; cb++) {
        const int c = cb*8 + (lane & 3)*2;
        *(float2*)&Ob[(size_t)r*CC + c] =
            make_float2(oacc[cb][0]*inv0, oacc[cb][1]*inv0);
        *(float2*)&Ob[(size_t)(r+8)*CC + c] =
            make_float2(oacc[cb][2]*inv1, oacc[cb][3]*inv1);
    }
}

// ---------------------------------------------------------------------------
// Proj conv: out[o][n] = sum_c Wp[o][c] * ot[n][c] + bp[o] + x[o][n]
// ---------------------------------------------------------------------------
__global__ __launch_bounds__(256) void proj_kernel(
    const float* __restrict__ W, const float* __restrict__ bias,
    const float* __restrict__ resid, float* __restrict__ out)
{
    const int b  = blockIdx.z;
    const int n0 = blockIdx.x * 64;
    const int o0 = blockIdx.y * 64;
    const float* Ht = g_ot + (size_t)b*NN*CC;  // [n][c]

    __shared__ __align__(16) float As[16][68];
    __shared__ __align__(16) float Bs[16][68];
    const int tid = threadIdx.x;
    const int tx = tid & 15, ty = tid >> 4;
    float acc[4][4] = {};

    for (int kc = 0; kc < CC; kc += 16) {
        {
            int o = tid >> 2, f4 = tid & 3;
            float4 w = *(const float4*)&W[(size_t)(o0+o)*CC + kc + f4*4];
            As[f4*4+0][o] = w.x; As[f4*4+1][o] = w.y;
            As[f4*4+2][o] = w.z; As[f4*4+3][o] = w.w;
        }
        {
            int np = tid >> 2, c4 = tid & 3;
            float4 v = *(const float4*)&Ht[(size_t)(n0+np)*CC + kc + c4*4];
            Bs[c4*4+0][np] = v.x; Bs[c4*4+1][np] = v.y;
            Bs[c4*4+2][np] = v.z; Bs[c4*4+3][np] = v.w;
        }
        __syncthreads();
        #pragma unroll
        for (int kk = 0; kk < 16; kk++) {
            float a[4], bb[4];
            *(float4*)a  = *(const float4*)&As[kk][ty*4];
            *(float4*)bb = *(const float4*)&Bs[kk][tx*4];
            #pragma unroll
            for (int i = 0; i < 4; i++)
                #pragma unroll
                for (int j = 0; j < 4; j++)
                    acc[i][j] = fmaf(a[i], bb[j], acc[i][j]);
        }
        __syncthreads();
    }

    const size_t ob = (size_t)b*CC*NN;
    #pragma unroll
    for (int i = 0; i < 4; i++) {
        const int o = o0 + ty*4 + i;
        const float bi = bias[o];
        const size_t rowoff = ob + (size_t)o*NN + n0 + tx*4;
        float4 r4 = *(const float4*)&resid[rowoff];
        float4 v;
        v.x = acc[i][0] + bi + r4.x; v.y = acc[i][1] + bi + r4.y;
        v.z = acc[i][2] + bi + r4.z; v.w = acc[i][3] + bi + r4.w;
        *(float4*)&out[rowoff] = v;
    }
}

// ---------------------------------------------------------------------------
extern "C" void kernel_launch(void* const* d_in, const int* in_sizes, int n_in,
                              void* d_out, int out_size) {
    const float* x   = (const float*)d_in[0];
    const float* gnw = (const float*)d_in[1];
    const float* gnb = (const float*)d_in[2];
    const float* wq  = (const float*)d_in[3];
    const float* bq  = (const float*)d_in[4];
    const float* wk  = (const float*)d_in[5];
    const float* bk  = (const float*)d_in[6];
    const float* wv  = (const float*)d_in[7];
    const float* bv  = (const float*)d_in[8];
    const float* wp  = (const float*)d_in[9];
    const float* bp  = (const float*)d_in[10];
    float* out = (float*)d_out;

    gn_kernel<<<BB*NG, 256>>>(x, gnw, gnb);

    dim3 cg(NN/64, CC/64, BB);
    conv_qkv_kernel<<<cg, 256>>>(wq, bq, wk, bk, wv, bv);

    const int smem_bytes = 5 * MBLK * LDK * sizeof(__nv_bfloat16);  // 87040
    cudaFuncSetAttribute(flash_kernel,
                         cudaFuncAttributeMaxDynamicSharedMemorySize, smem_bytes);
    dim3 fg(NN/MBLK, BB);
    flash_kernel<<<fg, 128, smem_bytes>>>();

    proj_kernel<<<cg, 256>>>(wp, bp, x, out);
}